// round 11
// baseline (speedup 1.0000x reference)
#include <cuda_runtime.h>
#include <cuda_bf16.h>

// Problem constants
#define BATCH   16
#define HDIM    224
#define WDIM    224
#define CDIM    64
#define HO      112
#define WO      112
#define NPATCH  (HO * WO)            // 12544 per image
#define TOPK    1254

// float4-unit strides for x [B,H,W,C] NHWC
#define IMG4    (HDIM * WDIM * (CDIM / 4))   // 802816
#define ROW4    (WDIM * (CDIM / 4))          // 3584
#define PIX4    (CDIM / 4)                   // 16
#define QTR4    (IMG4 / 4)                   // 200704 (56 rows)

#define NBINS   4096                 // top-12-bit histogram
#define MAXCAND 2048
#define CBLKS   392                  // conv blocks per image

// Scratch (no cudaMalloc allowed). Device globals are zero-initialized at
// module load; the tail-selector re-zeroes d_hist / d_arrive at its end, so
// every kernel_launch invocation starts clean (deterministic).
__device__ float    d_g[BATCH * NPATCH];
__device__ unsigned d_hist[BATCH * NBINS];
__device__ unsigned d_thr[BATCH];
__device__ unsigned d_arrive[BATCH];

// Order-preserving float->uint transform (ascending uint == ascending float)
__device__ __forceinline__ unsigned f2o(float f) {
    unsigned u = __float_as_uint(f);
    return (u & 0x80000000u) ? ~u : (u | 0x80000000u);
}

// Shared scratch for the tail selector (lives in every conv block; ~14KB)
struct SelShared {
    unsigned       cand_u[MAXCAND];
    unsigned short cand_i[MAXCAND];
    unsigned       partial[256];
    unsigned       wsum[8];
    unsigned       h2[256];
    unsigned       pref, rem, cnt, claim;
    int            is_last;
};

// ---------------------------------------------------------------------------
// Kernel 1: gating conv (2x2, stride 2, 1 out-channel), 4 patches per warp,
// fused top-12-bit histogram, PLUS tail-block per-image top-K threshold
// selection (the 392nd block of each image to arrive does the select).
// ---------------------------------------------------------------------------
__global__ void __launch_bounds__(256) conv_gate_k(
        const float* __restrict__ x, const float* __restrict__ wk) {
    __shared__ SelShared S;

    int b    = blockIdx.y;
    int warp = threadIdx.x >> 5;
    int lane = threadIdx.x & 31;
    int tid  = threadIdx.x;
    int q    = blockIdx.x * 8 + warp;      // quad index in [0, 3136)
    int ho   = q / 28;
    int wq   = q - ho * 28;

    const float4* x4 = (const float4*)x;
    const float4* w4 = (const float4*)wk;

    int r0 = b * IMG4 + (2 * ho) * ROW4 + (8 * wq) * PIX4;
    int r1 = r0 + ROW4;

    float4 wa = __ldg(&w4[lane]);
    float4 wb = __ldg(&w4[lane + 32]);

    float s[4];
    #pragma unroll
    for (int k = 0; k < 4; k++) {
        float4 a = __ldg(&x4[r0 + 32 * k + lane]);
        float4 c = __ldg(&x4[r1 + 32 * k + lane]);
        s[k] = a.x * wa.x + a.y * wa.y + a.z * wa.z + a.w * wa.w
             + c.x * wb.x + c.y * wb.y + c.z * wb.z + c.w * wb.w;
    }
    #pragma unroll
    for (int o = 16; o; o >>= 1) {
        #pragma unroll
        for (int k = 0; k < 4; k++)
            s[k] += __shfl_xor_sync(0xffffffffu, s[k], o);
    }
    if (lane < 4)
        atomicAdd(&d_hist[b * NBINS + (f2o(s[lane]) >> 20)], 1u);
    if (lane == 0) {
        float4* g4 = (float4*)d_g;
        g4[(b * NPATCH) / 4 + ho * 28 + wq] = make_float4(s[0], s[1], s[2], s[3]);
    }

    // ---- arrival: last block of this image becomes the selector ----
    // ALL threads fence their d_g/d_hist writes before tid 0 signals arrival
    // (canonical threadFenceReduction pattern).
    __threadfence();
    __syncthreads();
    if (tid == 0)
        S.is_last = (atomicAdd(&d_arrive[b], 1u) == CBLKS - 1);
    __syncthreads();
    if (!S.is_last) return;
    __threadfence();                       // acquire all d_g / d_hist writes

    const float* g = d_g + b * NPATCH;
    const unsigned* hist = d_hist + b * NBINS;

    // a) scan 4096-bin hist (16 bins/thread) from the top -> pref12 + rem
    unsigned psum = 0;
    #pragma unroll
    for (int k = 0; k < 16; k++) psum += hist[tid * 16 + k];
    S.partial[tid] = psum;
    unsigned ws = psum;
    #pragma unroll
    for (int o = 16; o; o >>= 1) ws += __shfl_xor_sync(0xffffffffu, ws, o);
    if (lane == 0) S.wsum[warp] = ws;
    __syncthreads();

    if (tid == 0) {
        int rem = TOPK;
        int w = 7;
        for (; w > 0; --w) { if (rem > (int)S.wsum[w]) rem -= (int)S.wsum[w]; else break; }
        int t = w * 32 + 31;
        for (; t > w * 32; --t) { if (rem > (int)S.partial[t]) rem -= (int)S.partial[t]; else break; }
        int d = t * 16 + 15;
        for (; d > t * 16; --d) { if (rem > (int)hist[d]) rem -= (int)hist[d]; else break; }
        S.pref = (unsigned)d;              // 12-bit prefix
        S.rem  = (unsigned)rem;
        S.cnt  = 0;
        S.claim = 0;
    }
    __syncthreads();

    // b) gather candidates whose top-12 bits match (d_g is L2-resident)
    unsigned pref12 = S.pref;
    for (int i = tid; i < NPATCH; i += 256) {
        unsigned u = f2o(g[i]);
        if ((u >> 20) == pref12) {
            unsigned pos = atomicAdd(&S.cnt, 1u);
            if (pos < MAXCAND) { S.cand_u[pos] = u; S.cand_i[pos] = (unsigned short)i; }
        }
    }
    __syncthreads();
    int cnt = min(S.cnt, (unsigned)MAXCAND);

    // c) byte-wise refine of the low 20 bits: bits[19:12], [11:4], [3:0]
    //    pass 1: bits 19:12
    S.h2[tid] = 0; __syncthreads();
    for (int i = tid; i < cnt; i += 256)
        atomicAdd(&S.h2[(S.cand_u[i] >> 12) & 255u], 1u);
    __syncthreads();
    if (tid == 0) {
        int rem = (int)S.rem; int d = 255;
        for (; d > 0; --d) { if (rem > (int)S.h2[d]) rem -= (int)S.h2[d]; else break; }
        S.pref = (S.pref << 8) | (unsigned)d;   // 20-bit prefix
        S.rem = (unsigned)rem;
    }
    __syncthreads();
    //    pass 2: bits 11:4
    unsigned pref20 = S.pref;
    S.h2[tid] = 0; __syncthreads();
    for (int i = tid; i < cnt; i += 256) {
        unsigned u = S.cand_u[i];
        if ((u >> 12) == pref20) atomicAdd(&S.h2[(u >> 4) & 255u], 1u);
    }
    __syncthreads();
    if (tid == 0) {
        int rem = (int)S.rem; int d = 255;
        for (; d > 0; --d) { if (rem > (int)S.h2[d]) rem -= (int)S.h2[d]; else break; }
        S.pref = (S.pref << 8) | (unsigned)d;   // 28-bit prefix
        S.rem = (unsigned)rem;
    }
    __syncthreads();
    //    pass 3: bits 3:0
    unsigned pref28 = S.pref;
    if (tid < 16) S.h2[tid] = 0;
    __syncthreads();
    for (int i = tid; i < cnt; i += 256) {
        unsigned u = S.cand_u[i];
        if ((u >> 4) == pref28) atomicAdd(&S.h2[u & 15u], 1u);
    }
    __syncthreads();
    if (tid == 0) {
        int rem = (int)S.rem; int d = 15;
        for (; d > 0; --d) { if (rem > (int)S.h2[d]) rem -= (int)S.h2[d]; else break; }
        S.pref = (S.pref << 4) | (unsigned)d;   // full 32-bit threshold
        S.rem = (unsigned)rem;
    }
    __syncthreads();

    // d) tie cleanup: keep exactly S.rem threshold-valued elements
    unsigned thr = S.pref, keep = S.rem;
    for (int i = tid; i < cnt; i += 256) {
        if (S.cand_u[i] == thr) {
            unsigned pcl = atomicAdd(&S.claim, 1u);
            if (pcl >= keep)
                d_g[b * NPATCH + S.cand_i[i]] = __uint_as_float(0xFF800000u); // -inf
        }
    }
    if (tid == 0) d_thr[b] = thr;

    // e) reset this image's histogram + arrival counter for the next call
    __syncthreads();
    #pragma unroll
    for (int k = 0; k < 16; k++)
        d_hist[b * NBINS + k * 256 + tid] = 0u;
    if (tid == 0) d_arrive[b] = 0u;
}

// ---------------------------------------------------------------------------
// Kernel 2: out = x * gate, ILP-8: two w-segments x 4 image quarters per
// thread. Gate computed inline from the RAW score via threshold compare.
// 32 consecutive float4 = one gate cell -> warp-uniform; zero cells skip
// the x read. Streaming stores (evict-first) for the never-re-read output.
// ---------------------------------------------------------------------------
__global__ void __launch_bounds__(256) apply_gate_k(
        const float* __restrict__ x, float* __restrict__ out) {
    int b   = blockIdx.y;
    int h   = blockIdx.x / 7;                       // 0..55 (quarter rows)
    int seg = blockIdx.x - h * 7;                   // 0..6
    int w0  = seg * 512 + threadIdx.x;              // first float4 col
    int w1  = w0 + 256;                             // second float4 col

    unsigned thr = __ldg(&d_thr[b]);
    const float* gb = d_g + b * NPATCH;
    int grow  = h >> 1;
    int gcol0 = w0 >> 5;
    int gcol1 = w1 >> 5;

    float gv[8];
    #pragma unroll
    for (int j = 0; j < 4; j++) {
        int gr = (grow + 28 * j) * WO;
        float s0 = __ldg(&gb[gr + gcol0]);
        float s1 = __ldg(&gb[gr + gcol1]);
        gv[j]     = (f2o(s0) >= thr) ? s0 : 0.0f;
        gv[j + 4] = (f2o(s1) >= thr) ? s1 : 0.0f;
    }

    int i0 = b * IMG4 + h * ROW4;
    const float4* x4 = (const float4*)x;
    float4*       o4 = (float4*)out;

    float4 r[8];
    #pragma unroll
    for (int j = 0; j < 4; j++) {
        float g0 = gv[j], g1 = gv[j + 4];
        int base = i0 + j * QTR4;
        if (g0 != 0.0f) {
            float4 v = __ldg(&x4[base + w0]);
            r[j] = make_float4(v.x * g0, v.y * g0, v.z * g0, v.w * g0);
        } else r[j] = make_float4(0.f, 0.f, 0.f, 0.f);
        if (g1 != 0.0f) {
            float4 v = __ldg(&x4[base + w1]);
            r[j + 4] = make_float4(v.x * g1, v.y * g1, v.z * g1, v.w * g1);
        } else r[j + 4] = make_float4(0.f, 0.f, 0.f, 0.f);
    }
    #pragma unroll
    for (int j = 0; j < 4; j++) {
        int base = i0 + j * QTR4;
        __stcs(&o4[base + w0], r[j]);
        __stcs(&o4[base + w1], r[j + 4]);
    }
}

// ---------------------------------------------------------------------------
extern "C" void kernel_launch(void* const* d_in, const int* in_sizes, int n_in,
                              void* d_out, int out_size) {
    const float* x  = (const float*)d_in[0];
    const float* wk = (const float*)d_in[1];
    float* out = (float*)d_out;

    // 1) conv + fused histogram + tail-block per-image threshold select
    dim3 cgrid(CBLKS, BATCH);
    conv_gate_k<<<cgrid, 256>>>(x, wk);

    // 2) apply gate, ILP-8, streaming stores
    dim3 agrid(7 * 56, BATCH);
    apply_gate_k<<<agrid, 256>>>(x, out);
}

// round 14
// speedup vs baseline: 1.0909x; 1.0909x over previous
#include <cuda_runtime.h>
#include <cuda_bf16.h>

// Problem constants
#define BATCH   16
#define HDIM    224
#define WDIM    224
#define CDIM    64
#define HO      112
#define WO      112
#define NPATCH  (HO * WO)            // 12544 per image
#define TOPK    1254

// float4-unit strides for x [B,H,W,C] NHWC
#define IMG4    (HDIM * WDIM * (CDIM / 4))   // 802816
#define ROW4    (WDIM * (CDIM / 4))          // 3584
#define PIX4    (CDIM / 4)                   // 16
#define QTR4    (IMG4 / 4)                   // 200704 (56 rows)

#define NBINS   4096                 // top-12-bit histogram
#define MAXCAND 2048

// Scratch (no cudaMalloc allowed). Device globals are zero-initialized at
// module load; findthr_k re-zeroes d_hist at its end, so the hist is clean
// at the start of EVERY kernel_launch invocation (deterministic).
__device__ float    d_g[BATCH * NPATCH];
__device__ unsigned d_hist[BATCH * NBINS];
__device__ unsigned d_thr[BATCH];

// Order-preserving float->uint transform (ascending uint == ascending float)
__device__ __forceinline__ unsigned f2o(float f) {
    unsigned u = __float_as_uint(f);
    return (u & 0x80000000u) ? ~u : (u | 0x80000000u);
}

// ---------------------------------------------------------------------------
// Kernel 1: gating conv (2x2, stride 2, 1 out-channel), 4 patches per warp,
// fused top-12-bit histogram accumulation (hidden under DRAM time).
// ---------------------------------------------------------------------------
__global__ void __launch_bounds__(256) conv_gate_k(
        const float* __restrict__ x, const float* __restrict__ wk) {
    int b    = blockIdx.y;
    int warp = threadIdx.x >> 5;
    int lane = threadIdx.x & 31;
    int q    = blockIdx.x * 8 + warp;      // quad index in [0, 3136)
    int ho   = q / 28;
    int wq   = q - ho * 28;

    const float4* x4 = (const float4*)x;
    const float4* w4 = (const float4*)wk;

    int r0 = b * IMG4 + (2 * ho) * ROW4 + (8 * wq) * PIX4;
    int r1 = r0 + ROW4;

    float4 wa = __ldg(&w4[lane]);
    float4 wb = __ldg(&w4[lane + 32]);

    float s[4];
    #pragma unroll
    for (int k = 0; k < 4; k++) {
        float4 a = __ldg(&x4[r0 + 32 * k + lane]);
        float4 c = __ldg(&x4[r1 + 32 * k + lane]);
        s[k] = a.x * wa.x + a.y * wa.y + a.z * wa.z + a.w * wa.w
             + c.x * wb.x + c.y * wb.y + c.z * wb.z + c.w * wb.w;
    }
    #pragma unroll
    for (int o = 16; o; o >>= 1) {
        #pragma unroll
        for (int k = 0; k < 4; k++)
            s[k] += __shfl_xor_sync(0xffffffffu, s[k], o);
    }
    if (lane < 4)
        atomicAdd(&d_hist[b * NBINS + (f2o(s[lane]) >> 20)], 1u);
    if (lane == 0) {
        float4* g4 = (float4*)d_g;
        g4[(b * NPATCH) / 4 + ho * 28 + wq] = make_float4(s[0], s[1], s[2], s[3]);
    }
}

// ---------------------------------------------------------------------------
// Kernel 2: per-image threshold finder. One block (1024 thr) per image.
//  a) scan 4096-bin hist from the top -> 12-bit prefix + rem
//  b) gather candidates in that bin from L2-resident d_g
//  c) BYTE-WISE refine of the low 20 bits (3 histogram passes, 9 barriers
//     total instead of the previous 60 bit-serial barrier rounds)
//  d) zero out excess ties in d_g (rare), publish d_thr[b]
//  e) re-zero this image's histogram for the next invocation
// ---------------------------------------------------------------------------
__global__ void __launch_bounds__(1024) findthr_k(void) {
    int b   = blockIdx.x;
    int tid = threadIdx.x;
    int lane = tid & 31, wid = tid >> 5;
    const float* g = d_g + b * NPATCH;
    const unsigned* hist = d_hist + b * NBINS;

    __shared__ unsigned partial[1024];
    __shared__ unsigned wsum[32];
    __shared__ unsigned h2[256];
    __shared__ unsigned s_pref, s_rem, s_cnt, s_claim;
    __shared__ unsigned cand_u[MAXCAND];
    __shared__ unsigned short cand_i[MAXCAND];

    // a) per-thread sum of 4 bins, warp sums, then serial top-down scan
    unsigned h0 = hist[tid * 4 + 0], h1 = hist[tid * 4 + 1];
    unsigned hh2 = hist[tid * 4 + 2], h3 = hist[tid * 4 + 3];
    unsigned p = h0 + h1 + hh2 + h3;
    partial[tid] = p;
    unsigned ws = p;
    #pragma unroll
    for (int o = 16; o; o >>= 1) ws += __shfl_xor_sync(0xffffffffu, ws, o);
    if (lane == 0) wsum[wid] = ws;
    __syncthreads();

    if (tid == 0) {
        int rem = TOPK;
        int w = 31;
        for (; w > 0; --w) { if (rem > (int)wsum[w]) rem -= (int)wsum[w]; else break; }
        int t = w * 32 + 31;
        for (; t > w * 32; --t) { if (rem > (int)partial[t]) rem -= (int)partial[t]; else break; }
        int d = t * 4 + 3;
        for (; d > t * 4; --d) { if (rem > (int)hist[d]) rem -= (int)hist[d]; else break; }
        s_pref = (unsigned)d;              // 12-bit prefix
        s_rem  = (unsigned)rem;
        s_cnt  = 0;
        s_claim = 0;
    }
    __syncthreads();

    // b) gather candidates whose top-12 bits match (d_g is L2-resident)
    unsigned pref12 = s_pref;
    for (int i = tid; i < NPATCH; i += 1024) {
        unsigned u = f2o(g[i]);
        if ((u >> 20) == pref12) {
            unsigned pos = atomicAdd(&s_cnt, 1u);
            if (pos < MAXCAND) { cand_u[pos] = u; cand_i[pos] = (unsigned short)i; }
        }
    }
    __syncthreads();
    int cnt = min(s_cnt, (unsigned)MAXCAND);

    // c) byte-wise refine: bits [19:12], [11:4], [3:0]
    //    pass 1: bits 19:12
    if (tid < 256) h2[tid] = 0;
    __syncthreads();
    for (int i = tid; i < cnt; i += 1024)
        atomicAdd(&h2[(cand_u[i] >> 12) & 255u], 1u);
    __syncthreads();
    if (tid == 0) {
        int rem = (int)s_rem; int d = 255;
        for (; d > 0; --d) { if (rem > (int)h2[d]) rem -= (int)h2[d]; else break; }
        s_pref = (s_pref << 8) | (unsigned)d;   // 20-bit prefix
        s_rem = (unsigned)rem;
    }
    __syncthreads();
    //    pass 2: bits 11:4
    unsigned pref20 = s_pref;
    if (tid < 256) h2[tid] = 0;
    __syncthreads();
    for (int i = tid; i < cnt; i += 1024) {
        unsigned u = cand_u[i];
        if ((u >> 12) == pref20) atomicAdd(&h2[(u >> 4) & 255u], 1u);
    }
    __syncthreads();
    if (tid == 0) {
        int rem = (int)s_rem; int d = 255;
        for (; d > 0; --d) { if (rem > (int)h2[d]) rem -= (int)h2[d]; else break; }
        s_pref = (s_pref << 8) | (unsigned)d;   // 28-bit prefix
        s_rem = (unsigned)rem;
    }
    __syncthreads();
    //    pass 3: bits 3:0
    unsigned pref28 = s_pref;
    if (tid < 16) h2[tid] = 0;
    __syncthreads();
    for (int i = tid; i < cnt; i += 1024) {
        unsigned u = cand_u[i];
        if ((u >> 4) == pref28) atomicAdd(&h2[u & 15u], 1u);
    }
    __syncthreads();
    if (tid == 0) {
        int rem = (int)s_rem; int d = 15;
        for (; d > 0; --d) { if (rem > (int)h2[d]) rem -= (int)h2[d]; else break; }
        s_pref = (s_pref << 4) | (unsigned)d;   // full 32-bit threshold
        s_rem = (unsigned)rem;
    }
    __syncthreads();

    // d) tie cleanup: keep exactly s_rem threshold-valued elements
    unsigned thr = s_pref, keep = s_rem;
    for (int i = tid; i < cnt; i += 1024) {
        if (cand_u[i] == thr) {
            unsigned pcl = atomicAdd(&s_claim, 1u);
            if (pcl >= keep)
                d_g[b * NPATCH + cand_i[i]] = __uint_as_float(0xFF800000u); // -inf
        }
    }
    if (tid == 0) d_thr[b] = thr;

    // e) re-zero this image's histogram bins for the next invocation
    __syncthreads();
    #pragma unroll
    for (int k = 0; k < NBINS / 1024; k++)
        d_hist[b * NBINS + k * 1024 + tid] = 0u;
}

// ---------------------------------------------------------------------------
// Kernel 3: out = x * gate, ILP-8: two w-segments x 4 image quarters per
// thread. Gate computed inline from the RAW score via threshold compare.
// 32 consecutive float4 = one gate cell -> warp-uniform; zero cells skip
// the x read. Streaming stores (evict-first) for the never-re-read output.
// ---------------------------------------------------------------------------
__global__ void __launch_bounds__(256) apply_gate_k(
        const float* __restrict__ x, float* __restrict__ out) {
    int b   = blockIdx.y;
    int h   = blockIdx.x / 7;                       // 0..55 (quarter rows)
    int seg = blockIdx.x - h * 7;                   // 0..6
    int w0  = seg * 512 + threadIdx.x;              // first float4 col
    int w1  = w0 + 256;                             // second float4 col

    unsigned thr = __ldg(&d_thr[b]);
    const float* gb = d_g + b * NPATCH;
    int grow  = h >> 1;
    int gcol0 = w0 >> 5;
    int gcol1 = w1 >> 5;

    float gv[8];
    #pragma unroll
    for (int j = 0; j < 4; j++) {
        int gr = (grow + 28 * j) * WO;
        float s0 = __ldg(&gb[gr + gcol0]);
        float s1 = __ldg(&gb[gr + gcol1]);
        gv[j]     = (f2o(s0) >= thr) ? s0 : 0.0f;
        gv[j + 4] = (f2o(s1) >= thr) ? s1 : 0.0f;
    }

    int i0 = b * IMG4 + h * ROW4;
    const float4* x4 = (const float4*)x;
    float4*       o4 = (float4*)out;

    float4 r[8];
    #pragma unroll
    for (int j = 0; j < 4; j++) {
        float g0 = gv[j], g1 = gv[j + 4];
        int base = i0 + j * QTR4;
        if (g0 != 0.0f) {
            float4 v = __ldg(&x4[base + w0]);
            r[j] = make_float4(v.x * g0, v.y * g0, v.z * g0, v.w * g0);
        } else r[j] = make_float4(0.f, 0.f, 0.f, 0.f);
        if (g1 != 0.0f) {
            float4 v = __ldg(&x4[base + w1]);
            r[j + 4] = make_float4(v.x * g1, v.y * g1, v.z * g1, v.w * g1);
        } else r[j + 4] = make_float4(0.f, 0.f, 0.f, 0.f);
    }
    #pragma unroll
    for (int j = 0; j < 4; j++) {
        int base = i0 + j * QTR4;
        __stcs(&o4[base + w0], r[j]);
        __stcs(&o4[base + w1], r[j + 4]);
    }
}

// ---------------------------------------------------------------------------
extern "C" void kernel_launch(void* const* d_in, const int* in_sizes, int n_in,
                              void* d_out, int out_size) {
    const float* x  = (const float*)d_in[0];
    const float* wk = (const float*)d_in[1];
    float* out = (float*)d_out;

    // 1) conv + fused histogram (hist arrives zeroed — see d_hist note)
    dim3 cgrid(392, BATCH);
    conv_gate_k<<<cgrid, 256>>>(x, wk);

    // 2) per-image threshold: hist scan + candidate gather + byte refine
    //    (also re-zeroes the histogram for the next invocation)
    findthr_k<<<BATCH, 1024>>>();

    // 3) apply gate, ILP-8, streaming stores
    dim3 agrid(7 * 56, BATCH);
    apply_gate_k<<<agrid, 256>>>(x, out);
}